// round 2
// baseline (speedup 1.0000x reference)
#include <cuda_runtime.h>
#include <cstdint>

#define B_SZ 4096
#define D_SZ 4096
#define W_SZ 4
#define H_SZ 512

// Scratch for h = silu(G @ w1): 4096 x 512 fp32 = 8 MB (static, allocation-free)
__device__ float g_h[B_SZ * H_SZ];

// ---------------------------------------------------------------------------
// helpers
// ---------------------------------------------------------------------------
__device__ __forceinline__ uint32_t f2tf(float x) {
    uint32_t r;
    asm("cvt.rna.tf32.f32 %0, %1;" : "=r"(r) : "f"(x));
    return r;
}

__device__ __forceinline__ void mma_tf32(float d[4], const uint32_t a[4], const uint32_t b[2]) {
    asm volatile(
        "mma.sync.aligned.m16n8k8.row.col.f32.tf32.tf32.f32 "
        "{%0,%1,%2,%3}, {%4,%5,%6,%7}, {%8,%9}, {%0,%1,%2,%3};\n"
        : "+f"(d[0]), "+f"(d[1]), "+f"(d[2]), "+f"(d[3])
        : "r"(a[0]), "r"(a[1]), "r"(a[2]), "r"(a[3]), "r"(b[0]), "r"(b[1]));
}

__device__ __forceinline__ float silu(float v) {
    return v * (1.0f / (1.0f + __expf(-v)));
}

// Block tile: BM=128, BN=64, BK=16. 256 threads = 8 warps (4x2 warp grid,
// each warp owns a 32x32 tile = 2 m-frags x 4 n-frags of m16n8k8).
// Shared layout (floats):
//   sA: 2 buffers of [16][129]  (k-major, padded)   -> 2*2064
//   sB: 2 buffers of [16][65]                       -> 2*1040
#define SA_STRIDE 129
#define SB_STRIDE 65
#define SA_BUF    (16 * SA_STRIDE)
#define SB_BUF    (16 * SB_STRIDE)
#define SMEM_MAINLOOP (2 * SA_BUF + 2 * SB_BUF)   // 6208 floats

__device__ __forceinline__ void gload(const float* __restrict__ A, int lda,
                                      const float* __restrict__ Bp, int ldb,
                                      int k0, float4 ra[2], float4& rb, int tid) {
#pragma unroll
    for (int j = 0; j < 2; j++) {
        int id = tid + 256 * j;
        int row = id >> 2;
        int col = (id & 3) * 4;
        ra[j] = *reinterpret_cast<const float4*>(A + (size_t)row * lda + k0 + col);
    }
    int brow = tid >> 4;
    int bcol = (tid & 15) * 4;
    rb = *reinterpret_cast<const float4*>(Bp + (size_t)(k0 + brow) * ldb + bcol);
}

__device__ __forceinline__ void sstore(float* sA, float* sB,
                                       const float4 ra[2], const float4 rb, int tid) {
#pragma unroll
    for (int j = 0; j < 2; j++) {
        int id = tid + 256 * j;
        int row = id >> 2;
        int col = (id & 3) * 4;
        sA[(col + 0) * SA_STRIDE + row] = ra[j].x;
        sA[(col + 1) * SA_STRIDE + row] = ra[j].y;
        sA[(col + 2) * SA_STRIDE + row] = ra[j].z;
        sA[(col + 3) * SA_STRIDE + row] = ra[j].w;
    }
    int brow = tid >> 4;
    int bcol = (tid & 15) * 4;
    float* p = sB + brow * SB_STRIDE + bcol;
    p[0] = rb.x; p[1] = rb.y; p[2] = rb.z; p[3] = rb.w;
}

__device__ __forceinline__ void compute_bk(const float* sA, const float* sB,
                                           float acc[2][4][4], int warpM, int warpN, int lane) {
    int g   = lane >> 2;
    int tig = lane & 3;
    int rowBase = warpM * 32 + g;
    int colBase = warpN * 32 + g;
#pragma unroll
    for (int ks = 0; ks < 2; ks++) {
        int k = ks * 8;
        uint32_t afr[2][4], bfr[4][2];
#pragma unroll
        for (int mt = 0; mt < 2; mt++) {
            int r = rowBase + mt * 16;
            afr[mt][0] = f2tf(sA[(k + tig) * SA_STRIDE + r]);
            afr[mt][1] = f2tf(sA[(k + tig) * SA_STRIDE + r + 8]);
            afr[mt][2] = f2tf(sA[(k + tig + 4) * SA_STRIDE + r]);
            afr[mt][3] = f2tf(sA[(k + tig + 4) * SA_STRIDE + r + 8]);
        }
#pragma unroll
        for (int nt = 0; nt < 4; nt++) {
            int c = colBase + nt * 8;
            bfr[nt][0] = f2tf(sB[(k + tig) * SB_STRIDE + c]);
            bfr[nt][1] = f2tf(sB[(k + tig + 4) * SB_STRIDE + c]);
        }
#pragma unroll
        for (int mt = 0; mt < 2; mt++)
#pragma unroll
            for (int nt = 0; nt < 4; nt++)
                mma_tf32(acc[mt][nt], afr[mt], bfr[nt]);
    }
}

__device__ __forceinline__ void gemm_mainloop(const float* __restrict__ A, int lda,
                                              const float* __restrict__ Bp, int ldb,
                                              int nIter, float* sA, float* sB,
                                              float acc[2][4][4],
                                              int tid, int warpM, int warpN, int lane) {
    float4 ra[2];
    float4 rb;
    gload(A, lda, Bp, ldb, 0, ra, rb, tid);
    sstore(sA, sB, ra, rb, tid);
    __syncthreads();
    for (int it = 0; it < nIter; it++) {
        int cur = it & 1;
        if (it + 1 < nIter) gload(A, lda, Bp, ldb, (it + 1) * 16, ra, rb, tid);
        compute_bk(sA + cur * SA_BUF, sB + cur * SB_BUF, acc, warpM, warpN, lane);
        if (it + 1 < nIter) {
            int nxt = cur ^ 1;
            sstore(sA + nxt * SA_BUF, sB + nxt * SB_BUF, ra, rb, tid);
        }
        __syncthreads();
    }
}

// ---------------------------------------------------------------------------
// Kernel 1: h = silu(G @ w1)   (M=4096, N=512, K=4096)
// ---------------------------------------------------------------------------
__global__ __launch_bounds__(256) void dsc_gemm1(const float* __restrict__ G,
                                                 const float* __restrict__ w1) {
    __shared__ __align__(16) float smem[SMEM_MAINLOOP];
    float* sA = smem;
    float* sB = smem + 2 * SA_BUF;

    int tid = threadIdx.x, lane = tid & 31, warp = tid >> 5;
    int warpM = warp >> 1, warpN = warp & 1;
    int bm = blockIdx.x, bn = blockIdx.y;

    const float* A  = G + (size_t)bm * 128 * D_SZ;
    const float* Bp = w1 + bn * 64;

    float acc[2][4][4] = {};
    gemm_mainloop(A, D_SZ, Bp, H_SZ, D_SZ / 16, sA, sB, acc, tid, warpM, warpN, lane);

    int g = lane >> 2, tig = lane & 3;
#pragma unroll
    for (int mt = 0; mt < 2; mt++) {
#pragma unroll
        for (int nt = 0; nt < 4; nt++) {
            int row = bm * 128 + warpM * 32 + mt * 16 + g;
            int col = bn * 64 + warpN * 32 + nt * 8 + 2 * tig;
            g_h[(size_t)row * H_SZ + col]           = silu(acc[mt][nt][0]);
            g_h[(size_t)row * H_SZ + col + 1]       = silu(acc[mt][nt][1]);
            g_h[(size_t)(row + 8) * H_SZ + col]     = silu(acc[mt][nt][2]);
            g_h[(size_t)(row + 8) * H_SZ + col + 1] = silu(acc[mt][nt][3]);
        }
    }
}

// ---------------------------------------------------------------------------
// Kernel 2: kernels = h @ w2 + b2, fused with cache shift + conv + silu.
// Block tile = 128 b-rows x 64 cols = 128 b x 16 d.  (M=4096, N=16384, K=512)
// ---------------------------------------------------------------------------
#define SC_STRIDE 72   // 128x72 floats = 36 KB; also covers mainloop's 6208 floats

__global__ __launch_bounds__(256) void dsc_gemm2_conv(const float* __restrict__ x,
                                                      const float* __restrict__ cache,
                                                      const float* __restrict__ w2,
                                                      const float* __restrict__ b2,
                                                      float* __restrict__ out,
                                                      float* __restrict__ new_cache) {
    __shared__ __align__(16) float smem[128 * SC_STRIDE];
    float* sA = smem;
    float* sB = smem + 2 * SA_BUF;

    int tid = threadIdx.x, lane = tid & 31, warp = tid >> 5;
    int warpM = warp >> 1, warpN = warp & 1;
    int bm = blockIdx.x, bn = blockIdx.y;

    const float* A  = g_h + (size_t)bm * 128 * H_SZ;
    const float* Bp = w2 + bn * 64;

    float acc[2][4][4] = {};
    gemm_mainloop(A, H_SZ, Bp, D_SZ * W_SZ, H_SZ / 16, sA, sB, acc, tid, warpM, warpN, lane);

    __syncthreads();  // mainloop reads done; reuse smem as C tile

    float* sC = smem;
    int g = lane >> 2, tig = lane & 3;
#pragma unroll
    for (int mt = 0; mt < 2; mt++) {
#pragma unroll
        for (int nt = 0; nt < 4; nt++) {
            int r = warpM * 32 + mt * 16 + g;
            int c = warpN * 32 + nt * 8 + 2 * tig;
            sC[r * SC_STRIDE + c]           = acc[mt][nt][0];
            sC[r * SC_STRIDE + c + 1]       = acc[mt][nt][1];
            sC[(r + 8) * SC_STRIDE + c]     = acc[mt][nt][2];
            sC[(r + 8) * SC_STRIDE + c + 1] = acc[mt][nt][3];
        }
    }
    __syncthreads();

    // Conv epilogue: 128 b x 16 d pairs -> 8 per thread
    const float4* cache4 = reinterpret_cast<const float4*>(cache);
    float4* ncache4      = reinterpret_cast<float4*>(new_cache);
    const float4* b2_4   = reinterpret_cast<const float4*>(b2);

    int d_local = tid & 15;
    int d = bn * 16 + d_local;
    float4 bias = b2_4[d];

#pragma unroll
    for (int i = 0; i < 8; i++) {
        int b_local = (tid >> 4) + i * 16;
        int b = bm * 128 + b_local;
        size_t bd = (size_t)b * D_SZ + d;

        float4 kv = *reinterpret_cast<const float4*>(sC + b_local * SC_STRIDE + d_local * 4);
        kv.x += bias.x; kv.y += bias.y; kv.z += bias.z; kv.w += bias.w;

        float4 c4 = cache4[bd];
        float xv  = x[bd];

        float nc0 = c4.y, nc1 = c4.z, nc2 = c4.w, nc3 = xv;
        float s = nc0 * kv.x + nc1 * kv.y + nc2 * kv.z + nc3 * kv.w;

        out[bd] = silu(s);
        ncache4[bd] = make_float4(nc0, nc1, nc2, nc3);
    }
}

// ---------------------------------------------------------------------------
// launch
// ---------------------------------------------------------------------------
extern "C" void kernel_launch(void* const* d_in, const int* in_sizes, int n_in,
                              void* d_out, int out_size) {
    const float* x     = (const float*)d_in[0];  // (B,1,D)
    const float* gi    = (const float*)d_in[1];  // (B,1,D)
    const float* cache = (const float*)d_in[2];  // (B,D,W)
    const float* w1    = (const float*)d_in[3];  // (D,H)
    const float* w2    = (const float*)d_in[4];  // (H,D*W)
    const float* b2    = (const float*)d_in[5];  // (D*W)

    float* out    = (float*)d_out;                       // (B,1,D)
    float* ncache = out + (size_t)B_SZ * D_SZ;           // (B,D,W)

    dsc_gemm1<<<dim3(32, 8), 256>>>(gi, w1);
    dsc_gemm2_conv<<<dim3(32, 256), 256>>>(x, cache, w2, b2, out, ncache);
}

// round 3
// speedup vs baseline: 2.0038x; 2.0038x over previous
#include <cuda_runtime.h>
#include <cstdint>

#define B_SZ 4096
#define D_SZ 4096
#define W_SZ 4
#define H_SZ 512

// Scratch for h = silu(G @ w1): 4096 x 512 fp32 = 8 MB
__device__ float g_h[B_SZ * H_SZ];

// ---------------------------------------------------------------------------
// Tiling: BM=128, BN=64, BK=16, 256 threads = 8 warps (4x2), warp tile 32x32.
// Shared: sA [m][16 + 4 pad] (stride 20), sB [k][64 + 8 pad] (stride 72).
//   afr LDS bank = (20g + tig) mod 32 -> conflict-free
//   bfr LDS bank = (8*tig + g) mod 32  -> conflict-free
// 3-stage cp.async pipeline.
// ---------------------------------------------------------------------------
#define BM 128
#define BN 64
#define BK 16
#define STAGES 3
#define SA_ST 20
#define SB_ST 72
#define SA_STAGE (BM * SA_ST)              // 2560 floats
#define SB_STAGE (BK * SB_ST)              // 1152 floats
#define SMEM_FLOATS (STAGES * (SA_STAGE + SB_STAGE))  // 11136 floats = 43.5 KB

__device__ __forceinline__ uint32_t f2tf(float x) {
    uint32_t r;
    asm("cvt.rna.tf32.f32 %0, %1;" : "=r"(r) : "f"(x));
    return r;
}

__device__ __forceinline__ void mma_tf32(float d[4], const uint32_t a[4], const uint32_t b[2]) {
    asm volatile(
        "mma.sync.aligned.m16n8k8.row.col.f32.tf32.tf32.f32 "
        "{%0,%1,%2,%3}, {%4,%5,%6,%7}, {%8,%9}, {%0,%1,%2,%3};\n"
        : "+f"(d[0]), "+f"(d[1]), "+f"(d[2]), "+f"(d[3])
        : "r"(a[0]), "r"(a[1]), "r"(a[2]), "r"(a[3]), "r"(b[0]), "r"(b[1]));
}

__device__ __forceinline__ float silu(float v) {
    return v * (1.0f / (1.0f + __expf(-v)));
}

__device__ __forceinline__ void cp16(float* dst_smem, const float* src) {
    uint32_t d = (uint32_t)__cvta_generic_to_shared(dst_smem);
    asm volatile("cp.async.cg.shared.global [%0], [%1], 16;\n"
                 :: "r"(d), "l"(src) : "memory");
}
__device__ __forceinline__ void cp_commit() {
    asm volatile("cp.async.commit_group;\n" ::: "memory");
}
template <int N>
__device__ __forceinline__ void cp_wait() {
    asm volatile("cp.async.wait_group %0;\n" :: "n"(N) : "memory");
}

__device__ __forceinline__ void load_stage(const float* __restrict__ A, int lda,
                                           const float* __restrict__ Bp, int ldb,
                                           int k0, float* sA_s, float* sB_s, int tid) {
#pragma unroll
    for (int j = 0; j < 2; j++) {
        int id = tid + 256 * j;
        int row = id >> 2;
        int c4 = (id & 3) * 4;
        cp16(sA_s + row * SA_ST + c4, A + (size_t)row * lda + k0 + c4);
    }
    int brow = tid >> 4;
    int bc4 = (tid & 15) * 4;
    cp16(sB_s + brow * SB_ST + bc4, Bp + (size_t)(k0 + brow) * ldb + bc4);
}

__device__ __forceinline__ void compute_bk(const float* sA, const float* sB,
                                           float acc[2][4][4], int warpM, int warpN, int lane) {
    int g = lane >> 2;
    int tig = lane & 3;
    int rowBase = warpM * 32 + g;
    int colBase = warpN * 32 + g;
#pragma unroll
    for (int ks = 0; ks < 2; ks++) {
        int k = ks * 8;
        uint32_t afr[2][4], bfr[4][2];
#pragma unroll
        for (int mt = 0; mt < 2; mt++) {
            int r = rowBase + mt * 16;
            afr[mt][0] = f2tf(sA[r * SA_ST + k + tig]);
            afr[mt][1] = f2tf(sA[(r + 8) * SA_ST + k + tig]);
            afr[mt][2] = f2tf(sA[r * SA_ST + k + tig + 4]);
            afr[mt][3] = f2tf(sA[(r + 8) * SA_ST + k + tig + 4]);
        }
#pragma unroll
        for (int nt = 0; nt < 4; nt++) {
            int c = colBase + nt * 8;
            bfr[nt][0] = f2tf(sB[(k + tig) * SB_ST + c]);
            bfr[nt][1] = f2tf(sB[(k + tig + 4) * SB_ST + c]);
        }
#pragma unroll
        for (int mt = 0; mt < 2; mt++)
#pragma unroll
            for (int nt = 0; nt < 4; nt++)
                mma_tf32(acc[mt][nt], afr[mt], bfr[nt]);
    }
}

__device__ __forceinline__ void gemm_mainloop(const float* __restrict__ A, int lda,
                                              const float* __restrict__ Bp, int ldb,
                                              int nIter, float* sA, float* sB,
                                              float acc[2][4][4],
                                              int tid, int warpM, int warpN, int lane) {
#pragma unroll
    for (int s = 0; s < STAGES - 1; s++) {
        if (s < nIter)
            load_stage(A, lda, Bp, ldb, s * BK, sA + s * SA_STAGE, sB + s * SB_STAGE, tid);
        cp_commit();
    }
    for (int it = 0; it < nIter; it++) {
        cp_wait<STAGES - 2>();
        __syncthreads();
        int nxt = it + STAGES - 1;
        if (nxt < nIter) {
            int buf = nxt % STAGES;
            load_stage(A, lda, Bp, ldb, nxt * BK, sA + buf * SA_STAGE, sB + buf * SB_STAGE, tid);
        }
        cp_commit();
        int cur = it % STAGES;
        compute_bk(sA + cur * SA_STAGE, sB + cur * SB_STAGE, acc, warpM, warpN, lane);
    }
}

// ---------------------------------------------------------------------------
// Kernel 1: h = silu(G @ w1)   (M=4096, N=512, K=4096)
// ---------------------------------------------------------------------------
__global__ __launch_bounds__(256, 2) void dsc_gemm1(const float* __restrict__ G,
                                                    const float* __restrict__ w1) {
    __shared__ __align__(16) float smem[SMEM_FLOATS];
    float* sA = smem;
    float* sB = smem + STAGES * SA_STAGE;

    int tid = threadIdx.x, lane = tid & 31, warp = tid >> 5;
    int warpM = warp >> 1, warpN = warp & 1;
    int bm = blockIdx.x, bn = blockIdx.y;

    const float* A = G + (size_t)bm * BM * D_SZ;
    const float* Bp = w1 + bn * BN;

    float acc[2][4][4] = {};
    gemm_mainloop(A, D_SZ, Bp, H_SZ, D_SZ / BK, sA, sB, acc, tid, warpM, warpN, lane);

    int g = lane >> 2, tig = lane & 3;
#pragma unroll
    for (int mt = 0; mt < 2; mt++) {
#pragma unroll
        for (int nt = 0; nt < 4; nt++) {
            int row = bm * BM + warpM * 32 + mt * 16 + g;
            int col = bn * BN + warpN * 32 + nt * 8 + 2 * tig;
            float2 v0 = make_float2(silu(acc[mt][nt][0]), silu(acc[mt][nt][1]));
            float2 v1 = make_float2(silu(acc[mt][nt][2]), silu(acc[mt][nt][3]));
            *reinterpret_cast<float2*>(g_h + (size_t)row * H_SZ + col) = v0;
            *reinterpret_cast<float2*>(g_h + (size_t)(row + 8) * H_SZ + col) = v1;
        }
    }
}

// ---------------------------------------------------------------------------
// Kernel 2: kernels = h @ w2 + b2, fused with cache shift + conv + silu.
// (M=4096, N=16384, K=512); block tile 128 b x 64 cols (= 128 b x 16 d)
// ---------------------------------------------------------------------------
#define SC_STRIDE 68   // 128*68 = 8704 floats <= SMEM_FLOATS

__global__ __launch_bounds__(256, 2) void dsc_gemm2_conv(const float* __restrict__ x,
                                                         const float* __restrict__ cache,
                                                         const float* __restrict__ w2,
                                                         const float* __restrict__ b2,
                                                         float* __restrict__ out,
                                                         float* __restrict__ new_cache) {
    __shared__ __align__(16) float smem[SMEM_FLOATS];
    float* sA = smem;
    float* sB = smem + STAGES * SA_STAGE;

    int tid = threadIdx.x, lane = tid & 31, warp = tid >> 5;
    int warpM = warp >> 1, warpN = warp & 1;
    int bm = blockIdx.x, bn = blockIdx.y;

    const float* A = g_h + (size_t)bm * BM * H_SZ;
    const float* Bp = w2 + bn * BN;

    float acc[2][4][4] = {};
    gemm_mainloop(A, H_SZ, Bp, D_SZ * W_SZ, H_SZ / BK, sA, sB, acc, tid, warpM, warpN, lane);

    __syncthreads();  // all compute done; reuse smem as C tile

    float* sC = smem;
    int g = lane >> 2, tig = lane & 3;
#pragma unroll
    for (int mt = 0; mt < 2; mt++) {
#pragma unroll
        for (int nt = 0; nt < 4; nt++) {
            int r = warpM * 32 + mt * 16 + g;
            int c = warpN * 32 + nt * 8 + 2 * tig;
            sC[r * SC_STRIDE + c] = acc[mt][nt][0];
            sC[r * SC_STRIDE + c + 1] = acc[mt][nt][1];
            sC[(r + 8) * SC_STRIDE + c] = acc[mt][nt][2];
            sC[(r + 8) * SC_STRIDE + c + 1] = acc[mt][nt][3];
        }
    }
    __syncthreads();

    // Conv epilogue: 128 b x 16 d -> 8 (b,d) pairs per thread
    const float4* cache4 = reinterpret_cast<const float4*>(cache);
    float4* ncache4 = reinterpret_cast<float4*>(new_cache);
    const float4* b2_4 = reinterpret_cast<const float4*>(b2);

    int d_local = tid & 15;
    int d = bn * 16 + d_local;
    float4 bias = b2_4[d];

#pragma unroll
    for (int i = 0; i < 8; i++) {
        int b_local = (tid >> 4) + i * 16;
        int b = bm * BM + b_local;
        size_t bd = (size_t)b * D_SZ + d;

        float4 kv = *reinterpret_cast<const float4*>(sC + b_local * SC_STRIDE + d_local * 4);
        kv.x += bias.x; kv.y += bias.y; kv.z += bias.z; kv.w += bias.w;

        float4 c4 = cache4[bd];
        float xv = x[bd];

        float nc0 = c4.y, nc1 = c4.z, nc2 = c4.w, nc3 = xv;
        float s = nc0 * kv.x + nc1 * kv.y + nc2 * kv.z + nc3 * kv.w;

        out[bd] = silu(s);
        ncache4[bd] = make_float4(nc0, nc1, nc2, nc3);
    }
}

// ---------------------------------------------------------------------------
// launch
// ---------------------------------------------------------------------------
extern "C" void kernel_launch(void* const* d_in, const int* in_sizes, int n_in,
                              void* d_out, int out_size) {
    const float* x     = (const float*)d_in[0];  // (B,1,D)
    const float* gi    = (const float*)d_in[1];  // (B,1,D)
    const float* cache = (const float*)d_in[2];  // (B,D,W)
    const float* w1    = (const float*)d_in[3];  // (D,H)
    const float* w2    = (const float*)d_in[4];  // (H,D*W)
    const float* b2    = (const float*)d_in[5];  // (D*W)

    float* out    = (float*)d_out;                 // (B,1,D)
    float* ncache = out + (size_t)B_SZ * D_SZ;     // (B,D,W)

    dsc_gemm1<<<dim3(32, 8), 256>>>(gi, w1);
    dsc_gemm2_conv<<<dim3(32, 256), 256>>>(x, cache, w2, b2, out, ncache);
}

// round 4
// speedup vs baseline: 2.4602x; 1.2278x over previous
#include <cuda_runtime.h>
#include <cstdint>

#define B_SZ 4096
#define D_SZ 4096
#define W_SZ 4
#define H_SZ 512

// Scratch: h (rounded to tf32 at store), tf32-rounded weights
__device__ float g_h[B_SZ * H_SZ];                 // 8 MB
__device__ float g_w1t[D_SZ * H_SZ];               // 8 MB
__device__ float g_w2t[H_SZ * D_SZ * W_SZ];        // 33.5 MB

// ---------------------------------------------------------------------------
// helpers
// ---------------------------------------------------------------------------
__device__ __forceinline__ uint32_t f2tf(float x) {
    uint32_t r;
    asm("cvt.rna.tf32.f32 %0, %1;" : "=r"(r) : "f"(x));
    return r;
}

__device__ __forceinline__ void mma_tf32(float d[4], const uint32_t a[4], const uint32_t b[2]) {
    asm volatile(
        "mma.sync.aligned.m16n8k8.row.col.f32.tf32.tf32.f32 "
        "{%0,%1,%2,%3}, {%4,%5,%6,%7}, {%8,%9}, {%0,%1,%2,%3};\n"
        : "+f"(d[0]), "+f"(d[1]), "+f"(d[2]), "+f"(d[3])
        : "r"(a[0]), "r"(a[1]), "r"(a[2]), "r"(a[3]), "r"(b[0]), "r"(b[1]));
}

__device__ __forceinline__ float silu(float v) {
    return v * (1.0f / (1.0f + __expf(-v)));
}

__device__ __forceinline__ void cp16(float* dst_smem, const float* src) {
    uint32_t d = (uint32_t)__cvta_generic_to_shared(dst_smem);
    asm volatile("cp.async.cg.shared.global [%0], [%1], 16;\n"
                 :: "r"(d), "l"(src) : "memory");
}
__device__ __forceinline__ void cp_commit() {
    asm volatile("cp.async.commit_group;\n" ::: "memory");
}
template <int N>
__device__ __forceinline__ void cp_wait() {
    asm volatile("cp.async.wait_group %0;\n" :: "n"(N) : "memory");
}

// ---------------------------------------------------------------------------
// Prepass: round weights to tf32 (stored as fp32 bit patterns)
// ---------------------------------------------------------------------------
__global__ __launch_bounds__(256) void tf32_round_kernel(const float* __restrict__ src,
                                                         float* __restrict__ dst, int n4) {
    int i = blockIdx.x * blockDim.x + threadIdx.x;
    if (i >= n4) return;
    float4 v = reinterpret_cast<const float4*>(src)[i];
    v.x = __uint_as_float(f2tf(v.x));
    v.y = __uint_as_float(f2tf(v.y));
    v.z = __uint_as_float(f2tf(v.z));
    v.w = __uint_as_float(f2tf(v.w));
    reinterpret_cast<float4*>(dst)[i] = v;
}

// ===========================================================================
// Kernel 1: h = silu(G @ w1)   (M=4096, N=512, K=4096)
// BM=128, BN=64, BK=16, 3 stages; 8 warps (4x2), warp tile 32x32.
// ===========================================================================
#define BK 16
#define STAGES 3

#define G1_BM 128
#define G1_BN 64
#define G1_SA_ST 20
#define G1_SB_ST 72
#define G1_SA_STAGE (G1_BM * G1_SA_ST)   // 2560
#define G1_SB_STAGE (BK * G1_SB_ST)      // 1152
#define G1_SMEM (STAGES * (G1_SA_STAGE + G1_SB_STAGE))

__global__ __launch_bounds__(256, 2) void dsc_gemm1(const float* __restrict__ G,
                                                    const float* __restrict__ w1) {
    __shared__ __align__(16) float smem[G1_SMEM];
    float* sA = smem;
    float* sB = smem + STAGES * G1_SA_STAGE;

    int tid = threadIdx.x, lane = tid & 31, warp = tid >> 5;
    int warpM = warp >> 1, warpN = warp & 1;
    int bm = blockIdx.x, bn = blockIdx.y;

    const float* A = G + (size_t)bm * G1_BM * D_SZ;
    const float* Bp = w1 + bn * G1_BN;

    float acc[2][4][4] = {};
    const int nIter = D_SZ / BK;

    auto load_stage = [&](int k0, float* sA_s, float* sB_s) {
#pragma unroll
        for (int j = 0; j < 2; j++) {
            int id = tid + 256 * j;
            int row = id >> 2;
            int c4 = (id & 3) * 4;
            cp16(sA_s + row * G1_SA_ST + c4, A + (size_t)row * D_SZ + k0 + c4);
        }
        int brow = tid >> 4;
        int bc4 = (tid & 15) * 4;
        cp16(sB_s + brow * G1_SB_ST + bc4, Bp + (size_t)(k0 + brow) * H_SZ + bc4);
    };

#pragma unroll
    for (int s = 0; s < STAGES - 1; s++) {
        load_stage(s * BK, sA + s * G1_SA_STAGE, sB + s * G1_SB_STAGE);
        cp_commit();
    }

    int g = lane >> 2, tig = lane & 3;
    for (int it = 0; it < nIter; it++) {
        cp_wait<STAGES - 2>();
        __syncthreads();
        int nxt = it + STAGES - 1;
        if (nxt < nIter) {
            int buf = nxt % STAGES;
            load_stage(nxt * BK, sA + buf * G1_SA_STAGE, sB + buf * G1_SB_STAGE);
        }
        cp_commit();
        const float* cA = sA + (it % STAGES) * G1_SA_STAGE;
        const float* cB = sB + (it % STAGES) * G1_SB_STAGE;
        int rowBase = warpM * 32 + g;
        int colBase = warpN * 32 + g;
#pragma unroll
        for (int ks = 0; ks < 2; ks++) {
            int k = ks * 8;
            uint32_t afr[2][4], bfr[4][2];
#pragma unroll
            for (int mt = 0; mt < 2; mt++) {
                int r = rowBase + mt * 16;
                afr[mt][0] = f2tf(cA[r * G1_SA_ST + k + tig]);
                afr[mt][1] = f2tf(cA[(r + 8) * G1_SA_ST + k + tig]);
                afr[mt][2] = f2tf(cA[r * G1_SA_ST + k + tig + 4]);
                afr[mt][3] = f2tf(cA[(r + 8) * G1_SA_ST + k + tig + 4]);
            }
#pragma unroll
            for (int nt = 0; nt < 4; nt++) {
                int c = colBase + nt * 8;
                bfr[nt][0] = __float_as_uint(cB[(k + tig) * G1_SB_ST + c]);      // pre-rounded
                bfr[nt][1] = __float_as_uint(cB[(k + tig + 4) * G1_SB_ST + c]);
            }
#pragma unroll
            for (int mt = 0; mt < 2; mt++)
#pragma unroll
                for (int nt = 0; nt < 4; nt++)
                    mma_tf32(acc[mt][nt], afr[mt], bfr[nt]);
        }
    }

    // store h = silu(acc), rounded to tf32 so gemm2 needs no cvt
#pragma unroll
    for (int mt = 0; mt < 2; mt++) {
#pragma unroll
        for (int nt = 0; nt < 4; nt++) {
            int row = bm * G1_BM + warpM * 32 + mt * 16 + g;
            int col = bn * G1_BN + warpN * 32 + nt * 8 + 2 * tig;
            float2 v0, v1;
            v0.x = __uint_as_float(f2tf(silu(acc[mt][nt][0])));
            v0.y = __uint_as_float(f2tf(silu(acc[mt][nt][1])));
            v1.x = __uint_as_float(f2tf(silu(acc[mt][nt][2])));
            v1.y = __uint_as_float(f2tf(silu(acc[mt][nt][3])));
            *reinterpret_cast<float2*>(g_h + (size_t)row * H_SZ + col) = v0;
            *reinterpret_cast<float2*>(g_h + (size_t)(row + 8) * H_SZ + col) = v1;
        }
    }
}

// ===========================================================================
// Kernel 2: kernels = h @ w2t + b2, fused conv epilogue.
// M=4096, N=16384, K=512. BM=128, BN=128, BK=16, 3 stages.
// 8 warps (2x4), warp tile 64x32. No CVT anywhere (inputs pre-rounded).
// ===========================================================================
#define G2_BM 128
#define G2_BN 128
#define G2_SA_ST 20
#define G2_SB_ST 136
#define G2_SA_STAGE (G2_BM * G2_SA_ST)   // 2560
#define G2_SB_STAGE (BK * G2_SB_ST)      // 2176
#define G2_SMEM_FLOATS (STAGES * (G2_SA_STAGE + G2_SB_STAGE))  // 14208 = 56832 B
#define SC_STRIDE 68                     // epilogue tile 128x68 = 8704 floats (fits)

extern __shared__ float g2_smem[];

__global__ __launch_bounds__(256, 2) void dsc_gemm2_conv(const float* __restrict__ x,
                                                         const float* __restrict__ cache,
                                                         const float* __restrict__ w2t,
                                                         const float* __restrict__ b2,
                                                         float* __restrict__ out,
                                                         float* __restrict__ new_cache) {
    float* sA = g2_smem;
    float* sB = g2_smem + STAGES * G2_SA_STAGE;

    int tid = threadIdx.x, lane = tid & 31, warp = tid >> 5;
    int warpM = warp >> 2, warpN = warp & 3;   // 2 x 4
    int bm = blockIdx.x, bn = blockIdx.y;

    const float* A = g_h + (size_t)bm * G2_BM * H_SZ;
    const float* Bp = w2t + bn * G2_BN;
    const int ldb = D_SZ * W_SZ;

    float acc[4][4][4] = {};
    const int nIter = H_SZ / BK;   // 32

    auto load_stage = [&](int k0, float* sA_s, float* sB_s) {
#pragma unroll
        for (int j = 0; j < 2; j++) {
            int id = tid + 256 * j;
            int row = id >> 2;
            int c4 = (id & 3) * 4;
            cp16(sA_s + row * G2_SA_ST + c4, A + (size_t)row * H_SZ + k0 + c4);
        }
#pragma unroll
        for (int j = 0; j < 2; j++) {
            int id = tid + 256 * j;
            int brow = id >> 5;
            int bc4 = (id & 31) * 4;
            cp16(sB_s + brow * G2_SB_ST + bc4, Bp + (size_t)(k0 + brow) * ldb + bc4);
        }
    };

#pragma unroll
    for (int s = 0; s < STAGES - 1; s++) {
        load_stage(s * BK, sA + s * G2_SA_STAGE, sB + s * G2_SB_STAGE);
        cp_commit();
    }

    int g = lane >> 2, tig = lane & 3;
    for (int it = 0; it < nIter; it++) {
        cp_wait<STAGES - 2>();
        __syncthreads();
        int nxt = it + STAGES - 1;
        if (nxt < nIter) {
            int buf = nxt % STAGES;
            load_stage(nxt * BK, sA + buf * G2_SA_STAGE, sB + buf * G2_SB_STAGE);
        }
        cp_commit();
        const float* cA = sA + (it % STAGES) * G2_SA_STAGE;
        const float* cB = sB + (it % STAGES) * G2_SB_STAGE;
        int rowBase = warpM * 64 + g;
        int colBase = warpN * 32 + g;
#pragma unroll
        for (int ks = 0; ks < 2; ks++) {
            int k = ks * 8;
            uint32_t afr[4][4], bfr[4][2];
#pragma unroll
            for (int mt = 0; mt < 4; mt++) {
                int r = rowBase + mt * 16;
                afr[mt][0] = __float_as_uint(cA[r * G2_SA_ST + k + tig]);
                afr[mt][1] = __float_as_uint(cA[(r + 8) * G2_SA_ST + k + tig]);
                afr[mt][2] = __float_as_uint(cA[r * G2_SA_ST + k + tig + 4]);
                afr[mt][3] = __float_as_uint(cA[(r + 8) * G2_SA_ST + k + tig + 4]);
            }
#pragma unroll
            for (int nt = 0; nt < 4; nt++) {
                int c = colBase + nt * 8;
                bfr[nt][0] = __float_as_uint(cB[(k + tig) * G2_SB_ST + c]);
                bfr[nt][1] = __float_as_uint(cB[(k + tig + 4) * G2_SB_ST + c]);
            }
#pragma unroll
            for (int mt = 0; mt < 4; mt++)
#pragma unroll
                for (int nt = 0; nt < 4; nt++)
                    mma_tf32(acc[mt][nt], afr[mt], bfr[nt]);
        }
    }

    __syncthreads();   // mainloop smem reads done; reuse as C tile

    // Epilogue in two 64-col passes (warpN {0,1} then {2,3})
    float* sC = g2_smem;
    const float4* cache4 = reinterpret_cast<const float4*>(cache);
    float4* ncache4 = reinterpret_cast<float4*>(new_cache);
    const float4* b2_4 = reinterpret_cast<const float4*>(b2);

#pragma unroll
    for (int p = 0; p < 2; p++) {
        if ((warpN >> 1) == p) {
            int colBase = (warpN & 1) * 32;
#pragma unroll
            for (int mt = 0; mt < 4; mt++) {
#pragma unroll
                for (int nt = 0; nt < 4; nt++) {
                    int r = warpM * 64 + mt * 16 + g;
                    int c = colBase + nt * 8 + 2 * tig;
                    sC[r * SC_STRIDE + c] = acc[mt][nt][0];
                    sC[r * SC_STRIDE + c + 1] = acc[mt][nt][1];
                    sC[(r + 8) * SC_STRIDE + c] = acc[mt][nt][2];
                    sC[(r + 8) * SC_STRIDE + c + 1] = acc[mt][nt][3];
                }
            }
        }
        __syncthreads();

        int d_local = tid & 15;
        int d = bn * 32 + p * 16 + d_local;
        float4 bias = b2_4[d];
#pragma unroll
        for (int i = 0; i < 8; i++) {
            int b_local = (tid >> 4) + i * 16;
            int b = bm * G2_BM + b_local;
            size_t bd = (size_t)b * D_SZ + d;

            float4 kv = *reinterpret_cast<const float4*>(sC + b_local * SC_STRIDE + d_local * 4);
            kv.x += bias.x; kv.y += bias.y; kv.z += bias.z; kv.w += bias.w;

            float4 c4 = cache4[bd];
            float xv = x[bd];

            float nc0 = c4.y, nc1 = c4.z, nc2 = c4.w, nc3 = xv;
            float s = nc0 * kv.x + nc1 * kv.y + nc2 * kv.z + nc3 * kv.w;

            out[bd] = silu(s);
            ncache4[bd] = make_float4(nc0, nc1, nc2, nc3);
        }
        __syncthreads();
    }
}

// ---------------------------------------------------------------------------
// launch
// ---------------------------------------------------------------------------
extern "C" void kernel_launch(void* const* d_in, const int* in_sizes, int n_in,
                              void* d_out, int out_size) {
    const float* x     = (const float*)d_in[0];  // (B,1,D)
    const float* gi    = (const float*)d_in[1];  // (B,1,D)
    const float* cache = (const float*)d_in[2];  // (B,D,W)
    const float* w1    = (const float*)d_in[3];  // (D,H)
    const float* w2    = (const float*)d_in[4];  // (H,D*W)
    const float* b2    = (const float*)d_in[5];  // (D*W)

    float* out    = (float*)d_out;                 // (B,1,D)
    float* ncache = out + (size_t)B_SZ * D_SZ;     // (B,D,W)

    static int smem_set = 0;
    if (!smem_set) {
        cudaFuncSetAttribute(dsc_gemm2_conv, cudaFuncAttributeMaxDynamicSharedMemorySize,
                             G2_SMEM_FLOATS * sizeof(float));
        smem_set = 1;
    }

    float* w1t; cudaGetSymbolAddress((void**)&w1t, g_w1t);
    float* w2t; cudaGetSymbolAddress((void**)&w2t, g_w2t);

    int n1 = D_SZ * H_SZ / 4;
    int n2 = H_SZ * D_SZ * W_SZ / 4;
    tf32_round_kernel<<<(n1 + 255) / 256, 256>>>(w1, w1t, n1);
    tf32_round_kernel<<<(n2 + 255) / 256, 256>>>(w2, w2t, n2);

    dsc_gemm1<<<dim3(32, 8), 256>>>(gi, w1);
    dsc_gemm2_conv<<<dim3(32, 128), 256, G2_SMEM_FLOATS * sizeof(float)>>>(
        x, cache, w2t, b2, out, ncache);
}

// round 6
// speedup vs baseline: 2.6463x; 1.0756x over previous
#include <cuda_runtime.h>
#include <cstdint>

#define B_SZ 4096
#define D_SZ 4096
#define W_SZ 4
#define H_SZ 512
#define BK 16

// Static scratch (allocation-free). All GEMM operands stored k-permuted:
// within each k-group of 8, storage order is [k0,k4,k1,k5,k2,k6,k3,k7],
// so a thread's mma fragment pair (k+tig, k+tig+4) is contiguous (LDS.64).
__device__ float g_h[B_SZ * H_SZ];            // tf32(silu(G@w1)), [b][h_perm]
__device__ float g_gt[B_SZ * D_SZ];           // tf32 G, [b][d_perm]
__device__ float g_w1t[H_SZ * D_SZ];          // tf32 w1^T, [h][d_perm]
__device__ float g_w2t[D_SZ * W_SZ * H_SZ];   // tf32 w2^T, [n][h_perm]

// ---------------------------------------------------------------------------
// helpers
// ---------------------------------------------------------------------------
__device__ __forceinline__ uint32_t f2tf(float x) {
    uint32_t r;
    asm("cvt.rna.tf32.f32 %0, %1;" : "=r"(r) : "f"(x));
    return r;
}

__device__ __forceinline__ void mma_tf32(float d[4], const uint32_t a[4], const uint32_t b[2]) {
    asm volatile(
        "mma.sync.aligned.m16n8k8.row.col.f32.tf32.tf32.f32 "
        "{%0,%1,%2,%3}, {%4,%5,%6,%7}, {%8,%9}, {%0,%1,%2,%3};\n"
        : "+f"(d[0]), "+f"(d[1]), "+f"(d[2]), "+f"(d[3])
        : "r"(a[0]), "r"(a[1]), "r"(a[2]), "r"(a[3]), "r"(b[0]), "r"(b[1]));
}

__device__ __forceinline__ float silu(float v) {
    return v * (1.0f / (1.0f + __expf(-v)));
}

__device__ __forceinline__ uint32_t smem_u32(const void* p) {
    uint32_t a;
    asm("{ .reg .u64 t; cvta.to.shared.u64 t, %1; cvt.u32.u64 %0, t; }" : "=r"(a) : "l"(p));
    return a;
}

__device__ __forceinline__ void cp16u(uint32_t dst_smem, const float* src) {
    asm volatile("cp.async.cg.shared.global [%0], [%1], 16;\n"
                 :: "r"(dst_smem), "l"(src) : "memory");
}
__device__ __forceinline__ void cp_commit() {
    asm volatile("cp.async.commit_group;\n" ::: "memory");
}
template <int N>
__device__ __forceinline__ void cp_wait() {
    asm volatile("cp.async.wait_group %0;\n" :: "n"(N) : "memory");
}

// Swizzled smem tile: row-major [row][16 floats], 16B chunk q stored at q^(row&3).
// LDS.64 of fragment pair at permuted k-pos p = ks*8 + 2*tig.
__device__ __forceinline__ uint2 lds64_sw(uint32_t base, int row, int ks, int tig) {
    uint32_t chunk = (uint32_t)((ks << 1) + (tig >> 1)) ^ (uint32_t)(row & 3);
    uint32_t addr = base + (uint32_t)row * 64u + (chunk << 4) + (uint32_t)((tig & 1) << 3);
    uint2 v;
    asm volatile("ld.shared.v2.b32 {%0,%1}, [%2];" : "=r"(v.x), "=r"(v.y) : "r"(addr));
    return v;
}

// pos(k) within an 8-group for the k-interleave
__device__ __forceinline__ int kperm_pos(int kg) {
    return ((kg & 3) << 1) | (kg >> 2);
}

// ---------------------------------------------------------------------------
// Prepass kernels
// ---------------------------------------------------------------------------
// round to tf32 + permute k-groups of 8 along the contiguous dim
__global__ __launch_bounds__(256) void round_permute(const float* __restrict__ src,
                                                     float* __restrict__ dst, int ngroups) {
    int i = blockIdx.x * blockDim.x + threadIdx.x;
    if (i >= ngroups) return;
    const float4* s = reinterpret_cast<const float4*>(src) + 2 * (size_t)i;
    float4 lo = s[0], hi = s[1];
    float4 o0, o1;
    o0.x = __uint_as_float(f2tf(lo.x)); o0.y = __uint_as_float(f2tf(hi.x));
    o0.z = __uint_as_float(f2tf(lo.y)); o0.w = __uint_as_float(f2tf(hi.y));
    o1.x = __uint_as_float(f2tf(lo.z)); o1.y = __uint_as_float(f2tf(hi.z));
    o1.z = __uint_as_float(f2tf(lo.w)); o1.w = __uint_as_float(f2tf(hi.w));
    float4* d = reinterpret_cast<float4*>(dst) + 2 * (size_t)i;
    d[0] = o0; d[1] = o1;
}

// src [R][C] -> dst [C][R], tf32 round, permute along R (the k-dim after transpose)
__global__ __launch_bounds__(256) void transpose_perm(const float* __restrict__ src,
                                                      float* __restrict__ dst, int R, int C) {
    __shared__ float t[32][33];
    int c0 = blockIdx.x * 32, r0 = blockIdx.y * 32;
    int tx = threadIdx.x, ty = threadIdx.y;
#pragma unroll
    for (int j = ty; j < 32; j += 8)
        t[j][tx] = src[(size_t)(r0 + j) * C + c0 + tx];
    __syncthreads();
    int px = (tx & ~7) | kperm_pos(tx & 7);
#pragma unroll
    for (int j = ty; j < 32; j += 8)
        dst[(size_t)(c0 + j) * R + r0 + px] = __uint_as_float(f2tf(t[tx][j]));
}

// ===========================================================================
// Kernel 1: h = tf32(silu(G @ w1))  M=4096 N=512 K=4096
// BM=128 BN=64 BK=16, 4-stage cp.async, warp grid 4x2, warp tile 32x32.
// ===========================================================================
#define S1 4
#define A_STG 8192                      // 128 rows * 64 B
#define B_STG1 4096                     // 64 rows * 64 B
#define G1_SMEM (S1 * (A_STG + B_STG1)) // 49152 B

extern __shared__ float dynsmem[];

__global__ __launch_bounds__(256, 2) void dsc_gemm1(const float* __restrict__ G,
                                                    const float* __restrict__ w1t) {
    uint32_t sb = smem_u32(dynsmem);
    uint32_t aS = sb, bS = sb + S1 * A_STG;

    int tid = threadIdx.x, lane = tid & 31, warp = tid >> 5;
    int warpM = warp >> 1, warpN = warp & 1;
    int g = lane >> 2, tig = lane & 3;
    int bm = blockIdx.x, bn = blockIdx.y;

    const float* A = G + (size_t)bm * 128 * D_SZ;
    const float* B = w1t + (size_t)bn * 64 * D_SZ;

    auto load_stage = [&](int j) {
        uint32_t a_s = aS + (j & (S1 - 1)) * A_STG;
        uint32_t b_s = bS + (j & (S1 - 1)) * B_STG1;
#pragma unroll
        for (int t = 0; t < 2; t++) {
            int id = tid + 256 * t;
            int r = id >> 2, q = id & 3;
            cp16u(a_s + r * 64 + ((q ^ (r & 3)) << 4), A + (size_t)r * D_SZ + j * BK + q * 4);
        }
        {
            int r = tid >> 2, q = tid & 3;
            cp16u(b_s + r * 64 + ((q ^ (r & 3)) << 4), B + (size_t)r * D_SZ + tid * 0 + j * BK + q * 4);
        }
    };

    const int nIter = D_SZ / BK;  // 256
#pragma unroll
    for (int s = 0; s < S1 - 1; s++) { load_stage(s); cp_commit(); }

    float acc[2][4][4] = {};
    for (int it = 0; it < nIter; it++) {
        cp_wait<S1 - 2>();
        __syncthreads();
        int nxt = it + S1 - 1;
        if (nxt < nIter) load_stage(nxt);
        cp_commit();
        uint32_t a_s = aS + (it & (S1 - 1)) * A_STG;
        uint32_t b_s = bS + (it & (S1 - 1)) * B_STG1;
#pragma unroll
        for (int ks = 0; ks < 2; ks++) {
            uint2 alo[2], ahi[2], bb[4];
#pragma unroll
            for (int mt = 0; mt < 2; mt++) {
                int r = warpM * 32 + mt * 16 + g;
                alo[mt] = lds64_sw(a_s, r, ks, tig);
                ahi[mt] = lds64_sw(a_s, r + 8, ks, tig);
            }
#pragma unroll
            for (int nt = 0; nt < 4; nt++) {
                int c = warpN * 32 + nt * 8 + g;
                bb[nt] = lds64_sw(b_s, c, ks, tig);
            }
#pragma unroll
            for (int mt = 0; mt < 2; mt++) {
                uint32_t a[4] = {alo[mt].x, ahi[mt].x, alo[mt].y, ahi[mt].y};
#pragma unroll
                for (int nt = 0; nt < 4; nt++) {
                    uint32_t b[2] = {bb[nt].x, bb[nt].y};
                    mma_tf32(acc[mt][nt], a, b);
                }
            }
        }
    }

    // store h with permuted columns (k-interleave for gemm2's benefit)
#pragma unroll
    for (int mt = 0; mt < 2; mt++) {
#pragma unroll
        for (int nt = 0; nt < 4; nt++) {
            int row = bm * 128 + warpM * 32 + mt * 16 + g;
            int cbase = bn * 64 + warpN * 32 + nt * 8;
            int kg = 2 * tig;
            int p0 = kperm_pos(kg), p1 = kperm_pos(kg + 1);
            g_h[(size_t)row * H_SZ + cbase + p0] = __uint_as_float(f2tf(silu(acc[mt][nt][0])));
            g_h[(size_t)row * H_SZ + cbase + p1] = __uint_as_float(f2tf(silu(acc[mt][nt][1])));
            g_h[(size_t)(row + 8) * H_SZ + cbase + p0] = __uint_as_float(f2tf(silu(acc[mt][nt][2])));
            g_h[(size_t)(row + 8) * H_SZ + cbase + p1] = __uint_as_float(f2tf(silu(acc[mt][nt][3])));
        }
    }
}

// ===========================================================================
// Kernel 2: kernels = h @ w2^T + b2, fused conv epilogue.
// M=4096 N=16384 K=512. BM=128 BN=128 BK=16, 4 stages, warp grid 2x4,
// warp tile 64x32.
// ===========================================================================
#define S2 4
#define B_STG2 8192
#define G2_SMEM (S2 * (A_STG + B_STG2))   // 65536 B
#define SC_STRIDE 68                      // epilogue pass tile 128x68 floats

__global__ __launch_bounds__(256, 2) void dsc_gemm2(const float* __restrict__ x,
                                                    const float* __restrict__ cache,
                                                    const float* __restrict__ w2t,
                                                    const float* __restrict__ b2,
                                                    float* __restrict__ out,
                                                    float* __restrict__ new_cache) {
    uint32_t sb = smem_u32(dynsmem);
    uint32_t aS = sb, bS = sb + S2 * A_STG;

    int tid = threadIdx.x, lane = tid & 31, warp = tid >> 5;
    int warpM = warp >> 2, warpN = warp & 3;
    int g = lane >> 2, tig = lane & 3;
    int bm = blockIdx.x, bn = blockIdx.y;

    const float* A = g_h + (size_t)bm * 128 * H_SZ;
    const float* B = w2t + (size_t)bn * 128 * H_SZ;

    auto load_stage = [&](int j) {
        uint32_t a_s = aS + (j & (S2 - 1)) * A_STG;
        uint32_t b_s = bS + (j & (S2 - 1)) * B_STG2;
#pragma unroll
        for (int t = 0; t < 2; t++) {
            int id = tid + 256 * t;
            int r = id >> 2, q = id & 3;
            cp16u(a_s + r * 64 + ((q ^ (r & 3)) << 4), A + (size_t)r * H_SZ + j * BK + q * 4);
        }
#pragma unroll
        for (int t = 0; t < 2; t++) {
            int id = tid + 256 * t;
            int r = id >> 2, q = id & 3;
            cp16u(b_s + r * 64 + ((q ^ (r & 3)) << 4), B + (size_t)r * H_SZ + j * BK + q * 4);
        }
    };

    const int nIter = H_SZ / BK;  // 32
#pragma unroll
    for (int s = 0; s < S2 - 1; s++) { load_stage(s); cp_commit(); }

    float acc[4][4][4] = {};
    for (int it = 0; it < nIter; it++) {
        cp_wait<S2 - 2>();
        __syncthreads();
        int nxt = it + S2 - 1;
        if (nxt < nIter) load_stage(nxt);
        cp_commit();
        uint32_t a_s = aS + (it & (S2 - 1)) * A_STG;
        uint32_t b_s = bS + (it & (S2 - 1)) * B_STG2;
#pragma unroll
        for (int ks = 0; ks < 2; ks++) {
            uint2 alo[4], ahi[4], bb[4];
#pragma unroll
            for (int mt = 0; mt < 4; mt++) {
                int r = warpM * 64 + mt * 16 + g;
                alo[mt] = lds64_sw(a_s, r, ks, tig);
                ahi[mt] = lds64_sw(a_s, r + 8, ks, tig);
            }
#pragma unroll
            for (int nt = 0; nt < 4; nt++) {
                int c = warpN * 32 + nt * 8 + g;
                bb[nt] = lds64_sw(b_s, c, ks, tig);
            }
#pragma unroll
            for (int mt = 0; mt < 4; mt++) {
                uint32_t a[4] = {alo[mt].x, ahi[mt].x, alo[mt].y, ahi[mt].y};
#pragma unroll
                for (int nt = 0; nt < 4; nt++) {
                    uint32_t b[2] = {bb[nt].x, bb[nt].y};
                    mma_tf32(acc[mt][nt], a, b);
                }
            }
        }
    }

    __syncthreads();  // mainloop smem reads done; reuse as C tile

    // Epilogue in two 64-col passes (warpN {0,1} then {2,3})
    float* sC = dynsmem;
    const float4* cache4 = reinterpret_cast<const float4*>(cache);
    float4* ncache4 = reinterpret_cast<float4*>(new_cache);
    const float4* b2_4 = reinterpret_cast<const float4*>(b2);

#pragma unroll
    for (int p = 0; p < 2; p++) {
        if ((warpN >> 1) == p) {
            int colBase = (warpN & 1) * 32;
#pragma unroll
            for (int mt = 0; mt < 4; mt++) {
#pragma unroll
                for (int nt = 0; nt < 4; nt++) {
                    int r = warpM * 64 + mt * 16 + g;
                    int c = colBase + nt * 8 + 2 * tig;
                    sC[r * SC_STRIDE + c] = acc[mt][nt][0];
                    sC[r * SC_STRIDE + c + 1] = acc[mt][nt][1];
                    sC[(r + 8) * SC_STRIDE + c] = acc[mt][nt][2];
                    sC[(r + 8) * SC_STRIDE + c + 1] = acc[mt][nt][3];
                }
            }
        }
        __syncthreads();

        int d_local = tid & 15;
        int d = bn * 32 + p * 16 + d_local;
        float4 bias = b2_4[d];
#pragma unroll
        for (int i = 0; i < 8; i++) {
            int b_local = (tid >> 4) + i * 16;
            int b = bm * 128 + b_local;
            size_t bd = (size_t)b * D_SZ + d;

            float4 kv = *reinterpret_cast<const float4*>(sC + b_local * SC_STRIDE + d_local * 4);
            kv.x += bias.x; kv.y += bias.y; kv.z += bias.z; kv.w += bias.w;

            float4 c4 = cache4[bd];
            float xv = x[bd];

            float nc0 = c4.y, nc1 = c4.z, nc2 = c4.w, nc3 = xv;
            float s = nc0 * kv.x + nc1 * kv.y + nc2 * kv.z + nc3 * kv.w;

            out[bd] = silu(s);
            ncache4[bd] = make_float4(nc0, nc1, nc2, nc3);
        }
        __syncthreads();
    }
}

// ---------------------------------------------------------------------------
// launch
// ---------------------------------------------------------------------------
extern "C" void kernel_launch(void* const* d_in, const int* in_sizes, int n_in,
                              void* d_out, int out_size) {
    const float* x     = (const float*)d_in[0];  // (B,1,D)
    const float* gi    = (const float*)d_in[1];  // (B,1,D)
    const float* cache = (const float*)d_in[2];  // (B,D,W)
    const float* w1    = (const float*)d_in[3];  // (D,H)
    const float* w2    = (const float*)d_in[4];  // (H,D*W)
    const float* b2    = (const float*)d_in[5];  // (D*W)

    float* out    = (float*)d_out;               // (B,1,D)
    float* ncache = out + (size_t)B_SZ * D_SZ;   // (B,D,W)

    cudaFuncSetAttribute(dsc_gemm1, cudaFuncAttributeMaxDynamicSharedMemorySize, G1_SMEM);
    cudaFuncSetAttribute(dsc_gemm2, cudaFuncAttributeMaxDynamicSharedMemorySize, G2_SMEM);

    float* gt;  cudaGetSymbolAddress((void**)&gt,  g_gt);
    float* w1t; cudaGetSymbolAddress((void**)&w1t, g_w1t);
    float* w2t; cudaGetSymbolAddress((void**)&w2t, g_w2t);

    // Prepass: round+permute G along D; transpose+round+permute w1 -> [H][Dp],
    // w2 -> [D*W][Hp]
    int ng = B_SZ * D_SZ / 8;
    round_permute<<<(ng + 255) / 256, 256>>>(gi, gt, ng);
    transpose_perm<<<dim3(H_SZ / 32, D_SZ / 32), dim3(32, 8)>>>(w1, w1t, D_SZ, H_SZ);
    transpose_perm<<<dim3(D_SZ * W_SZ / 32, H_SZ / 32), dim3(32, 8)>>>(w2, w2t, H_SZ, D_SZ * W_SZ);

    dsc_gemm1<<<dim3(32, 8), 256, G1_SMEM>>>(gt, w1t);
    dsc_gemm2<<<dim3(32, 128), 256, G2_SMEM>>>(x, cache, w2t, b2, out, ncache);
}